// round 1
// baseline (speedup 1.0000x reference)
#include <cuda_runtime.h>
#include <cuda_bf16.h>
#include <cstdint>
#include <cstddef>

// Problem constants
#define BATCH 4
#define SEQ   2048
#define DIM   1024
#define SOFTMAX_SCALE 0.03125f  // 1/sqrt(1024)

// GEMM tiling
#define BM 128
#define BN 128
#define BK 16
#define AST 20    // BK + 4 pad  -> conflict-free fragment loads
#define BNS 136   // BN + 8 pad  -> conflict-free NN B-fragment loads

// Scratch (device globals; allocation in kernel_launch is forbidden)
__device__ float g_q[BATCH * SEQ * DIM];
__device__ float g_k[BATCH * SEQ * DIM];
__device__ float g_dots[(size_t)BATCH * SEQ * SEQ];

__device__ __forceinline__ uint32_t f2tf(float f) {
    uint32_t u;
    asm("cvt.rna.tf32.f32 %0, %1;" : "=r"(u) : "f"(f));
    return u;
}

__device__ __forceinline__ void mma8(float* d, const uint32_t* a, const uint32_t* b) {
    asm volatile(
        "mma.sync.aligned.m16n8k8.row.col.f32.tf32.tf32.f32 "
        "{%0,%1,%2,%3},{%4,%5,%6,%7},{%8,%9},{%0,%1,%2,%3};"
        : "+f"(d[0]), "+f"(d[1]), "+f"(d[2]), "+f"(d[3])
        : "r"(a[0]), "r"(a[1]), "r"(a[2]), "r"(a[3]), "r"(b[0]), "r"(b[1]));
}

// ---------------------------------------------------------------------------
// GEMM "TT": C[i,j] = sum_k A[i,k] * B[j,k]   (A: [M,K] row-major, B: [N,K] row-major)
// Used for: Q/K projections (X @ W^T + bias) and the QK^T logits GEMM.
// ---------------------------------------------------------------------------
__global__ void __launch_bounds__(256, 2) gemm_tt_kernel(
    const float* __restrict__ A, const float* __restrict__ B,
    const float* __restrict__ bias, float* __restrict__ C,
    int M, int N, int K,
    size_t strideA, size_t strideB, size_t strideC)
{
    A += (size_t)blockIdx.z * strideA;
    B += (size_t)blockIdx.z * strideB;
    C += (size_t)blockIdx.z * strideC;

    const int tid  = threadIdx.x;
    const int lane = tid & 31;
    const int warp = tid >> 5;
    const int wm0  = (warp >> 2) * 64;   // warp row base within block tile
    const int wn0  = (warp & 3) * 32;    // warp col base within block tile
    const int brow = blockIdx.y * BM;
    const int bcol = blockIdx.x * BN;

    __shared__ float As[2][BM * AST];
    __shared__ float Bs[2][BM * AST];

    // Global load mapping: 128x16 tile = 512 float4, 256 threads -> 2 each.
    const int r0 = tid >> 2;            // 0..63
    const int c0 = (tid & 3) * 4;       // 0,4,8,12
    const float* Ag = A + (size_t)(brow + r0) * K + c0;
    const float* Bg = B + (size_t)(bcol + r0) * K + c0;

    float4 pa0, pa1, pb0, pb1;

    const int nk = K / BK;

    // prefetch tile 0
    {
        pa0 = *(const float4*)(Ag);
        pa1 = *(const float4*)(Ag + (size_t)64 * K);
        pb0 = *(const float4*)(Bg);
        pb1 = *(const float4*)(Bg + (size_t)64 * K);
        *(float4*)&As[0][r0 * AST + c0]        = pa0;
        *(float4*)&As[0][(r0 + 64) * AST + c0] = pa1;
        *(float4*)&Bs[0][r0 * AST + c0]        = pb0;
        *(float4*)&Bs[0][(r0 + 64) * AST + c0] = pb1;
    }
    __syncthreads();

    float acc[4][4][4] = {};

    for (int kt = 0; kt < nk; kt++) {
        const int cur = kt & 1;
        if (kt + 1 < nk) {
            size_t off = (size_t)(kt + 1) * BK;
            pa0 = *(const float4*)(Ag + off);
            pa1 = *(const float4*)(Ag + off + (size_t)64 * K);
            pb0 = *(const float4*)(Bg + off);
            pb1 = *(const float4*)(Bg + off + (size_t)64 * K);
        }

        #pragma unroll
        for (int ks = 0; ks < BK; ks += 8) {
            uint32_t af[4][4], bf[4][2];
            #pragma unroll
            for (int mf = 0; mf < 4; mf++) {
                int row = wm0 + mf * 16 + (lane >> 2);
                int col = ks + (lane & 3);
                const float* p = &As[cur][row * AST + col];
                af[mf][0] = f2tf(p[0]);
                af[mf][1] = f2tf(p[8 * AST]);
                af[mf][2] = f2tf(p[4]);
                af[mf][3] = f2tf(p[8 * AST + 4]);
            }
            #pragma unroll
            for (int nf = 0; nf < 4; nf++) {
                int row = wn0 + nf * 8 + (lane >> 2);
                int col = ks + (lane & 3);
                const float* p = &Bs[cur][row * AST + col];
                bf[nf][0] = f2tf(p[0]);
                bf[nf][1] = f2tf(p[4]);
            }
            #pragma unroll
            for (int mf = 0; mf < 4; mf++)
                #pragma unroll
                for (int nf = 0; nf < 4; nf++)
                    mma8(acc[mf][nf], af[mf], bf[nf]);
        }

        if (kt + 1 < nk) {
            const int nxt = 1 - cur;
            *(float4*)&As[nxt][r0 * AST + c0]        = pa0;
            *(float4*)&As[nxt][(r0 + 64) * AST + c0] = pa1;
            *(float4*)&Bs[nxt][r0 * AST + c0]        = pb0;
            *(float4*)&Bs[nxt][(r0 + 64) * AST + c0] = pb1;
        }
        __syncthreads();
    }

    // Epilogue
    #pragma unroll
    for (int mf = 0; mf < 4; mf++) {
        int r = brow + wm0 + mf * 16 + (lane >> 2);
        #pragma unroll
        for (int nf = 0; nf < 4; nf++) {
            int cidx = bcol + wn0 + nf * 8 + (lane & 3) * 2;
            float b0 = 0.f, b1 = 0.f;
            if (bias) { b0 = bias[cidx]; b1 = bias[cidx + 1]; }
            float2 v0 = make_float2(acc[mf][nf][0] + b0, acc[mf][nf][1] + b1);
            float2 v1 = make_float2(acc[mf][nf][2] + b0, acc[mf][nf][3] + b1);
            *(float2*)&C[(size_t)r * N + cidx]       = v0;
            *(float2*)&C[(size_t)(r + 8) * N + cidx] = v1;
        }
    }
}

// ---------------------------------------------------------------------------
// GEMM "NN": C[i,j] = sum_k A[i,k] * B[k,j]   (A: [M,K] row-major, B: [K,N] row-major)
// Used for: out = attn @ value.
// ---------------------------------------------------------------------------
__global__ void __launch_bounds__(256, 2) gemm_nn_kernel(
    const float* __restrict__ A, const float* __restrict__ B,
    float* __restrict__ C,
    int M, int N, int K,
    size_t strideA, size_t strideB, size_t strideC)
{
    A += (size_t)blockIdx.z * strideA;
    B += (size_t)blockIdx.z * strideB;
    C += (size_t)blockIdx.z * strideC;

    const int tid  = threadIdx.x;
    const int lane = tid & 31;
    const int warp = tid >> 5;
    const int wm0  = (warp >> 2) * 64;
    const int wn0  = (warp & 3) * 32;
    const int brow = blockIdx.y * BM;
    const int bcol = blockIdx.x * BN;

    __shared__ float As[2][BM * AST];
    __shared__ float Bs[2][BK * BNS];

    // A-side load mapping (same as TT)
    const int r0 = tid >> 2;
    const int c0 = (tid & 3) * 4;
    const float* Ag = A + (size_t)(brow + r0) * K + c0;

    // B-side: tile is BK(16) rows x BN(128) cols; 512 float4, 2 per thread.
    const int rB = tid >> 5;          // 0..7 (second load: +8)
    const int cB = (tid & 31) * 4;    // 0..124
    const float* Bg = B + (size_t)rB * N + bcol + cB;

    float4 pa0, pa1, pb0, pb1;
    const int nk = K / BK;

    {
        pa0 = *(const float4*)(Ag);
        pa1 = *(const float4*)(Ag + (size_t)64 * K);
        pb0 = *(const float4*)(Bg);
        pb1 = *(const float4*)(Bg + (size_t)8 * N);
        *(float4*)&As[0][r0 * AST + c0]        = pa0;
        *(float4*)&As[0][(r0 + 64) * AST + c0] = pa1;
        *(float4*)&Bs[0][rB * BNS + cB]        = pb0;
        *(float4*)&Bs[0][(rB + 8) * BNS + cB]  = pb1;
    }
    __syncthreads();

    float acc[4][4][4] = {};

    for (int kt = 0; kt < nk; kt++) {
        const int cur = kt & 1;
        if (kt + 1 < nk) {
            size_t offA = (size_t)(kt + 1) * BK;
            size_t offB = (size_t)(kt + 1) * BK * N;
            pa0 = *(const float4*)(Ag + offA);
            pa1 = *(const float4*)(Ag + offA + (size_t)64 * K);
            pb0 = *(const float4*)(Bg + offB);
            pb1 = *(const float4*)(Bg + offB + (size_t)8 * N);
        }

        #pragma unroll
        for (int ks = 0; ks < BK; ks += 8) {
            uint32_t af[4][4], bf[4][2];
            #pragma unroll
            for (int mf = 0; mf < 4; mf++) {
                int row = wm0 + mf * 16 + (lane >> 2);
                int col = ks + (lane & 3);
                const float* p = &As[cur][row * AST + col];
                af[mf][0] = f2tf(p[0]);
                af[mf][1] = f2tf(p[8 * AST]);
                af[mf][2] = f2tf(p[4]);
                af[mf][3] = f2tf(p[8 * AST + 4]);
            }
            #pragma unroll
            for (int nf = 0; nf < 4; nf++) {
                int kk = ks + (lane & 3);
                int nn = wn0 + nf * 8 + (lane >> 2);
                const float* p = &Bs[cur][kk * BNS + nn];
                bf[nf][0] = f2tf(p[0]);
                bf[nf][1] = f2tf(p[4 * BNS]);
            }
            #pragma unroll
            for (int mf = 0; mf < 4; mf++)
                #pragma unroll
                for (int nf = 0; nf < 4; nf++)
                    mma8(acc[mf][nf], af[mf], bf[nf]);
        }

        if (kt + 1 < nk) {
            const int nxt = 1 - cur;
            *(float4*)&As[nxt][r0 * AST + c0]        = pa0;
            *(float4*)&As[nxt][(r0 + 64) * AST + c0] = pa1;
            *(float4*)&Bs[nxt][rB * BNS + cB]        = pb0;
            *(float4*)&Bs[nxt][(rB + 8) * BNS + cB]  = pb1;
        }
        __syncthreads();
    }

    #pragma unroll
    for (int mf = 0; mf < 4; mf++) {
        int r = brow + wm0 + mf * 16 + (lane >> 2);
        #pragma unroll
        for (int nf = 0; nf < 4; nf++) {
            int cidx = bcol + wn0 + nf * 8 + (lane & 3) * 2;
            float2 v0 = make_float2(acc[mf][nf][0], acc[mf][nf][1]);
            float2 v1 = make_float2(acc[mf][nf][2], acc[mf][nf][3]);
            *(float2*)&C[(size_t)r * N + cidx]       = v0;
            *(float2*)&C[(size_t)(r + 8) * N + cidx] = v1;
        }
    }
}

// ---------------------------------------------------------------------------
// Row softmax over 2048 cols, scale folded in: softmax(scale * x), in place.
// ---------------------------------------------------------------------------
__global__ void softmax_kernel(float* __restrict__ x)
{
    const int row = blockIdx.x;
    float* p = x + (size_t)row * SEQ;
    const int tid = threadIdx.x;

    float v[8];
    float m = -1e30f;
    #pragma unroll
    for (int i = 0; i < 8; i++) {
        v[i] = p[tid + i * 256];
        m = fmaxf(m, v[i]);
    }

    __shared__ float red[8];
    #pragma unroll
    for (int o = 16; o; o >>= 1) m = fmaxf(m, __shfl_xor_sync(0xffffffffu, m, o));
    if ((tid & 31) == 0) red[tid >> 5] = m;
    __syncthreads();
    m = red[0];
    #pragma unroll
    for (int i = 1; i < 8; i++) m = fmaxf(m, red[i]);
    __syncthreads();

    float s = 0.f;
    #pragma unroll
    for (int i = 0; i < 8; i++) {
        v[i] = __expf((v[i] - m) * SOFTMAX_SCALE);
        s += v[i];
    }
    #pragma unroll
    for (int o = 16; o; o >>= 1) s += __shfl_xor_sync(0xffffffffu, s, o);
    if ((tid & 31) == 0) red[tid >> 5] = s;
    __syncthreads();
    s = red[0];
    #pragma unroll
    for (int i = 1; i < 8; i++) s += red[i];
    float inv = 1.0f / s;

    #pragma unroll
    for (int i = 0; i < 8; i++) p[tid + i * 256] = v[i] * inv;
}

// ---------------------------------------------------------------------------
extern "C" void kernel_launch(void* const* d_in, const int* in_sizes, int n_in,
                              void* d_out, int out_size)
{
    const float* query = (const float*)d_in[0];
    const float* key_in = (const float*)d_in[1];
    const float* value = (const float*)d_in[2];
    const float* Wq = (const float*)d_in[3];
    const float* bq = (const float*)d_in[4];
    const float* Wk = (const float*)d_in[5];
    const float* bk = (const float*)d_in[6];
    // Wv/bv (d_in[7], d_in[8]) are intentionally unused (reference quirk).
    float* out = (float*)d_out;

    float *q, *k, *dots;
    cudaGetSymbolAddress((void**)&q, g_q);
    cudaGetSymbolAddress((void**)&k, g_k);
    cudaGetSymbolAddress((void**)&dots, g_dots);

    dim3 blk(256);

    // 1) q = query @ Wq^T + bq   (M=8192, N=1024, K=1024)
    gemm_tt_kernel<<<dim3(DIM / BN, (BATCH * SEQ) / BM, 1), blk>>>(
        query, Wq, bq, q, BATCH * SEQ, DIM, DIM, 0, 0, 0);

    // 2) k = key_in @ Wk^T + bk
    gemm_tt_kernel<<<dim3(DIM / BN, (BATCH * SEQ) / BM, 1), blk>>>(
        key_in, Wk, bk, k, BATCH * SEQ, DIM, DIM, 0, 0, 0);

    // 3) dots[b] = q[b] @ k[b]^T   (M=N=2048, K=1024), batched over z
    gemm_tt_kernel<<<dim3(SEQ / BN, SEQ / BM, BATCH), blk>>>(
        q, k, nullptr, dots, SEQ, SEQ, DIM,
        (size_t)SEQ * DIM, (size_t)SEQ * DIM, (size_t)SEQ * SEQ);

    // 4) softmax rows (scale folded in)
    softmax_kernel<<<BATCH * SEQ, 256>>>(dots);

    // 5) out[b] = attn[b] @ value[b]   (M=2048, N=1024, K=2048)
    gemm_nn_kernel<<<dim3(DIM / BN, SEQ / BM, BATCH), blk>>>(
        dots, value, out, SEQ, DIM, SEQ,
        (size_t)SEQ * SEQ, (size_t)SEQ * DIM, (size_t)SEQ * DIM);
}

// round 4
// speedup vs baseline: 2.4168x; 2.4168x over previous
#include <cuda_runtime.h>
#include <cuda_bf16.h>
#include <cstdint>
#include <cstddef>

// Problem constants
#define BATCH 4
#define SEQ   2048
#define DIM   1024
#define SOFTMAX_SCALE 0.03125f  // 1/sqrt(1024)

// ---------------------------------------------------------------------------
// tcgen05 availability: only in arch-specific ('a' / family) compile passes.
// Plain compute_103 pass falls back to legacy mma.sync (validated Round 1).
// ---------------------------------------------------------------------------
#if defined(__CUDA_ARCH__) && (__CUDA_ARCH__ >= 1000) && \
    (defined(__CUDA_ARCH_FEAT_SM103_ALL) || defined(__CUDA_ARCH_FEAT_SM100_ALL) || \
     defined(__CUDA_ARCH_FEAT_SM101_ALL) || defined(__CUDA_ARCH_FAMILY_SPECIFIC__))
#define HAS_TCGEN05 1
#else
#define HAS_TCGEN05 0
#endif

// Host-side launch geometry: grid covers 128x128 output tiles.
// TC variant: even blockIdx.x computes 128x256 (odd CTAs exit).
#define TILE 128
#define NSTAGE 4

// TC smem layout (bytes, within dynamic smem)
#define SMEM_TMEM   0
#define SMEM_EMPTY(s) (16 + 8 * (s))
#define SMEM_DONE   48
#define SMEM_A(s)   (1024 + (s) * 16384)                  // 128 rows x 128B
#define SMEM_B(s)   (1024 + 4 * 16384 + (s) * 32768)      // 256 rows x 128B
#define SMEM_TOTAL  (1024 + 4 * 16384 + 4 * 32768)        // 197632

// instruction descriptor: kind::tf32, D=f32, A=B=tf32 (enc 2), K-major, M=128, N=256
#define MMA_IDESC ((1u << 4) | (2u << 7) | (2u << 10) | (32u << 17) | (8u << 24))

// ---------------------------------------------------------------------------
// Scratch (device globals; allocation in kernel_launch is forbidden)
// ---------------------------------------------------------------------------
__device__ float g_qr[BATCH * SEQ * DIM];   // query, tf32-rounded
__device__ float g_kr[BATCH * SEQ * DIM];   // key_in, tf32-rounded
__device__ float g_wq[DIM * DIM];           // Wq, tf32-rounded
__device__ float g_wk[DIM * DIM];           // Wk, tf32-rounded
__device__ float g_vt[BATCH * SEQ * DIM];   // value transposed [B][D][S], rounded
__device__ float g_q [BATCH * SEQ * DIM];   // projected q
__device__ float g_k [BATCH * SEQ * DIM];   // projected k
__device__ float g_dots[(size_t)BATCH * SEQ * SEQ];

// ---------------------------------------------------------------------------
// Common helpers
// ---------------------------------------------------------------------------
__device__ __forceinline__ float tf32r(float f) {
    uint32_t u;
    asm("cvt.rna.tf32.f32 %0, %1;" : "=r"(u) : "f"(f));
    return __uint_as_float(u);
}

__device__ __forceinline__ uint32_t f2tf(float f) {
    uint32_t u;
    asm("cvt.rna.tf32.f32 %0, %1;" : "=r"(u) : "f"(f));
    return u;
}

__device__ __forceinline__ uint32_t smem_u32(const void* p) {
    uint32_t a;
    asm("{ .reg .u64 t; cvta.to.shared.u64 t, %1; cvt.u32.u64 %0, t; }" : "=r"(a) : "l"(p));
    return a;
}

#if HAS_TCGEN05
// ---------------------------------------------------------------------------
// tcgen05-only helpers (compiled only in arch-specific pass)
// ---------------------------------------------------------------------------
__device__ __forceinline__ uint32_t elect_one_pred() {
    uint32_t pred;
    asm volatile(
        "{\n\t.reg .pred p;\n\t"
        "elect.sync _|p, 0xFFFFFFFF;\n\t"
        "selp.b32 %0, 1, 0, p;\n\t}"
        : "=r"(pred));
    return pred;
}

#define MBARRIER_INIT(addr, cnt) \
    asm volatile("mbarrier.init.shared.b64 [%0], %1;" :: "r"((uint32_t)(addr)), "r"((uint32_t)(cnt)) : "memory")

#define MBARRIER_WAIT_PARITY(addr, parity) do {                                        \
    uint32_t _mbar = (uint32_t)(addr);                                                 \
    uint32_t _par  = (uint32_t)(parity);                                               \
    uint32_t _done;                                                                    \
    asm volatile(                                                                      \
        "{\n\t.reg .pred p;\n\t"                                                       \
        "mbarrier.try_wait.parity.acquire.cta.shared::cta.b64 p, [%1], %2;\n\t"        \
        "selp.b32 %0, 1, 0, p;\n\t}"                                                   \
        : "=r"(_done) : "r"(_mbar), "r"(_par) : "memory");                             \
    if (!_done) {                                                                      \
        asm volatile(                                                                  \
            "{\n\t.reg .pred P1;\n\t"                                                  \
            "WAIT_LOOP_%=:\n\t"                                                        \
            "mbarrier.try_wait.parity.acquire.cta.shared::cta.b64 P1, [%0], %1, 0x989680;\n\t" \
            "@P1 bra.uni WAIT_DONE_%=;\n\t"                                            \
            "bra.uni WAIT_LOOP_%=;\n\t"                                                 \
            "WAIT_DONE_%=:\n\t}"                                                        \
            :: "r"(_mbar), "r"(_par) : "memory");                                      \
    }                                                                                  \
} while (0)

#define TCGEN05_ALLOC(smem_addr, ncols) \
    asm volatile("tcgen05.alloc.cta_group::1.sync.aligned.shared::cta.b32 [%0], %1;" \
        :: "r"((uint32_t)(smem_addr)), "r"((uint32_t)(ncols)) : "memory")
#define TCGEN05_DEALLOC(tmem, ncols) \
    asm volatile("tcgen05.dealloc.cta_group::1.sync.aligned.b32 %0, %1;" :: "r"(tmem), "r"((uint32_t)(ncols)))
#define TCGEN05_RELINQUISH() \
    asm volatile("tcgen05.relinquish_alloc_permit.cta_group::1.sync.aligned;")
#define TCGEN05_COMMIT(mbar) \
    asm volatile("tcgen05.commit.cta_group::1.mbarrier::arrive::one.shared::cluster.b64 [%0];" \
        :: "r"((uint32_t)(mbar)) : "memory")
#define TCGEN05_FENCE_AFTER()  asm volatile("tcgen05.fence::after_thread_sync;"  ::: "memory")
#define TCGEN05_FENCE_BEFORE() asm volatile("tcgen05.fence::before_thread_sync;" ::: "memory")
#define TCGEN05_WAIT_LD()      asm volatile("tcgen05.wait::ld.sync.aligned;"     ::: "memory")

#define CP_ASYNC16(sm, g) \
    asm volatile("cp.async.cg.shared.global [%0], [%1], 16;" :: "r"(sm), "l"(g))
#define CP_ASYNC_COMMIT() asm volatile("cp.async.commit_group;" ::: "memory")
#define CP_ASYNC_WAIT3()  asm volatile("cp.async.wait_group 3;" ::: "memory")

#define LDTM_X32(r, addr)                                                              \
    asm volatile(                                                                      \
        "tcgen05.ld.sync.aligned.32x32b.x32.b32 "                                      \
        "{%0, %1, %2, %3, %4, %5, %6, %7, "                                            \
        " %8, %9, %10, %11, %12, %13, %14, %15, "                                      \
        " %16, %17, %18, %19, %20, %21, %22, %23, "                                    \
        " %24, %25, %26, %27, %28, %29, %30, %31}, [%32];"                             \
        : "=r"((r)[0]),  "=r"((r)[1]),  "=r"((r)[2]),  "=r"((r)[3]),                   \
          "=r"((r)[4]),  "=r"((r)[5]),  "=r"((r)[6]),  "=r"((r)[7]),                   \
          "=r"((r)[8]),  "=r"((r)[9]),  "=r"((r)[10]), "=r"((r)[11]),                  \
          "=r"((r)[12]), "=r"((r)[13]), "=r"((r)[14]), "=r"((r)[15]),                  \
          "=r"((r)[16]), "=r"((r)[17]), "=r"((r)[18]), "=r"((r)[19]),                  \
          "=r"((r)[20]), "=r"((r)[21]), "=r"((r)[22]), "=r"((r)[23]),                  \
          "=r"((r)[24]), "=r"((r)[25]), "=r"((r)[26]), "=r"((r)[27]),                  \
          "=r"((r)[28]), "=r"((r)[29]), "=r"((r)[30]), "=r"((r)[31])                   \
        : "r"(addr))

static constexpr uint64_t DESC_SW128 =
    (2ull << 61) | (1ull << 46) | (64ull << 32) | (1ull << 16);

__device__ __forceinline__ uint64_t make_desc(uint32_t addr) {
    return DESC_SW128 | ((uint64_t)(addr >> 4) & 0x3FFF);
}

__device__ __forceinline__ void mma_tf32(uint32_t d_tmem, uint64_t ad, uint64_t bd,
                                         uint32_t idesc, bool acc) {
    uint32_t en = acc ? 1u : 0u;
    asm volatile(
        "{\n\t.reg .pred p;\n\t"
        "setp.ne.u32 p, %5, 0;\n\t"
        "tcgen05.mma.cta_group::1.kind::tf32 [%0], %1, %2, %3, {%4, %4, %4, %4}, p;\n\t}"
        :: "r"(d_tmem), "l"(ad), "l"(bd), "r"(idesc), "r"(0u), "r"(en)
        : "memory");
}
#else
// ---------------------------------------------------------------------------
// Legacy mma.sync helper (plain-arch fallback pass)
// ---------------------------------------------------------------------------
__device__ __forceinline__ void mma8(float* d, const uint32_t* a, const uint32_t* b) {
    asm volatile(
        "mma.sync.aligned.m16n8k8.row.col.f32.tf32.tf32.f32 "
        "{%0,%1,%2,%3},{%4,%5,%6,%7},{%8,%9},{%0,%1,%2,%3};"
        : "+f"(d[0]), "+f"(d[1]), "+f"(d[2]), "+f"(d[3])
        : "r"(a[0]), "r"(a[1]), "r"(a[2]), "r"(a[3]), "r"(b[0]), "r"(b[1]));
}
#endif

// ---------------------------------------------------------------------------
// Unified GEMM: C[i,j] = sum_k A[i,k] * B[j,k]  (both K-major fp32)
// Grid: (N/128, M/128, Z), 256 threads, dyn smem = SMEM_TOTAL.
//   tcgen05 pass : even blockIdx.x computes a 128x256 tile; odd CTAs exit.
//   fallback pass: every CTA computes its 128x128 tile via mma.sync tf32.
// ---------------------------------------------------------------------------
__global__ void __launch_bounds__(256, 1) gemm_u_kernel(
    const float* __restrict__ A, const float* __restrict__ B,
    const float* __restrict__ bias, float* __restrict__ C,
    int lda, int ldb, int ldc, int nk,
    size_t sA, size_t sB, size_t sC, int round_out)
{
    extern __shared__ char smem[];
    A += (size_t)blockIdx.z * sA;
    B += (size_t)blockIdx.z * sB;
    C += (size_t)blockIdx.z * sC;
    const int tid  = threadIdx.x;
    const int wid  = tid >> 5;
    const int lane = tid & 31;

#if HAS_TCGEN05
    // ======================= tcgen05 variant (128 x 256) ====================
    if (blockIdx.x & 1) return;
    const int brow = blockIdx.y * TILE;
    const int bcol = blockIdx.x * TILE;     // covers bcol .. bcol+255
    const uint32_t sb = smem_u32(smem);

    if (tid == 0) {
        #pragma unroll
        for (int s = 0; s < NSTAGE; s++) MBARRIER_INIT(sb + SMEM_EMPTY(s), 1);
        MBARRIER_INIT(sb + SMEM_DONE, 1);
    }
    if (wid == 0) TCGEN05_ALLOC(sb + SMEM_TMEM, 256);
    __syncthreads();

    uint32_t tmem;
    asm volatile("ld.shared.b32 %0, [%1];" : "=r"(tmem) : "r"(sb + SMEM_TMEM));

    auto load_stage = [&](int s, int kit) {
        const int kbase = kit * 32;
        const uint32_t a_s = sb + SMEM_A(s);
        const uint32_t b_s = sb + SMEM_B(s);
        #pragma unroll
        for (int j = 0; j < 4; j++) {        // A: 128 rows x 8 chunks = 1024
            int c   = tid + j * 256;
            int row = c >> 3;
            int co  = (c & 7) << 4;
            const float* g = A + (size_t)(brow + row) * lda + kbase + ((c & 7) << 2);
            CP_ASYNC16(a_s + (row << 7) + (co ^ ((row & 7) << 4)), g);
        }
        #pragma unroll
        for (int j = 0; j < 8; j++) {        // B: 256 rows x 8 chunks = 2048
            int c   = tid + j * 256;
            int row = c >> 3;
            int co  = (c & 7) << 4;
            const float* g = B + (size_t)(bcol + row) * ldb + kbase + ((c & 7) << 2);
            CP_ASYNC16(b_s + (row << 7) + (co ^ ((row & 7) << 4)), g);
        }
    };

    #pragma unroll
    for (int p = 0; p < NSTAGE - 1; p++) {
        if (p < nk) load_stage(p, p);
        CP_ASYNC_COMMIT();
    }

    for (int it = 0; it < nk; it++) {
        const int lit = it + (NSTAGE - 1);
        if (lit < nk) {
            const int s = lit & (NSTAGE - 1);
            if (lit >= NSTAGE)
                MBARRIER_WAIT_PARITY(sb + SMEM_EMPTY(s), ((lit >> 2) - 1) & 1);
            load_stage(s, lit);
        }
        CP_ASYNC_COMMIT();
        CP_ASYNC_WAIT3();
        asm volatile("fence.proxy.async.shared::cta;" ::: "memory");
        __syncthreads();

        if (wid == 1 && elect_one_pred()) {
            const int s = it & (NSTAGE - 1);
            uint64_t ad = make_desc(sb + SMEM_A(s));
            uint64_t bd = make_desc(sb + SMEM_B(s));
            #pragma unroll
            for (int st = 0; st < 4; st++)   // 4 x (K=8) = K-tile of 32
                mma_tf32(tmem, ad + st * 2, bd + st * 2, MMA_IDESC, (it | st) != 0);
            TCGEN05_COMMIT(sb + SMEM_EMPTY(s));
        }
    }

    if (wid == 1 && elect_one_pred()) TCGEN05_COMMIT(sb + SMEM_DONE);
    MBARRIER_WAIT_PARITY(sb + SMEM_DONE, 0);
    TCGEN05_FENCE_AFTER();

    // Epilogue: warps 0-3 -> cols 0..127, warps 4-7 -> cols 128..255.
    {
        const int row  = brow + (wid & 3) * 32 + lane;
        const int cof  = (wid >> 2) * 128;
        float* crow = C + (size_t)row * ldc + bcol + cof;
        #pragma unroll 1
        for (int cb = 0; cb < 4; cb++) {
            uint32_t d[32];
            LDTM_X32(d, tmem + cof + cb * 32);
            TCGEN05_WAIT_LD();
            #pragma unroll
            for (int j = 0; j < 32; j += 4) {
                float4 v;
                v.x = __uint_as_float(d[j + 0]);
                v.y = __uint_as_float(d[j + 1]);
                v.z = __uint_as_float(d[j + 2]);
                v.w = __uint_as_float(d[j + 3]);
                if (bias) {
                    const float4 bv = *(const float4*)&bias[bcol + cof + cb * 32 + j];
                    v.x += bv.x; v.y += bv.y; v.z += bv.z; v.w += bv.w;
                }
                if (round_out) {
                    v.x = tf32r(v.x); v.y = tf32r(v.y);
                    v.z = tf32r(v.z); v.w = tf32r(v.w);
                }
                *(float4*)(crow + cb * 32 + j) = v;
            }
        }
    }

    TCGEN05_FENCE_BEFORE();
    __syncthreads();
    if (wid == 0) {
        TCGEN05_RELINQUISH();
        TCGEN05_DEALLOC(tmem, 256);
    }

#else
    // ===================== legacy mma.sync variant (128 x 128) ==============
    #define BK 16
    #define AST 20
    const int wm0  = (wid >> 2) * 64;
    const int wn0  = (wid & 3) * 32;
    const int brow = blockIdx.y * TILE;
    const int bcol = blockIdx.x * TILE;
    const int K    = nk * 32;
    const int nk2  = K / BK;

    float* As = (float*)smem;            // 2 buffers x 128*20
    float* Bs = As + 2 * TILE * AST;

    const int r0 = tid >> 2;
    const int c0 = (tid & 3) * 4;
    const float* Ag = A + (size_t)(brow + r0) * lda + c0;
    const float* Bg = B + (size_t)(bcol + r0) * ldb + c0;

    float4 pa0, pa1, pb0, pb1;
    {
        pa0 = *(const float4*)(Ag);
        pa1 = *(const float4*)(Ag + (size_t)64 * lda);
        pb0 = *(const float4*)(Bg);
        pb1 = *(const float4*)(Bg + (size_t)64 * ldb);
        *(float4*)&As[r0 * AST + c0]        = pa0;
        *(float4*)&As[(r0 + 64) * AST + c0] = pa1;
        *(float4*)&Bs[r0 * AST + c0]        = pb0;
        *(float4*)&Bs[(r0 + 64) * AST + c0] = pb1;
    }
    __syncthreads();

    float acc[4][4][4] = {};

    for (int kt = 0; kt < nk2; kt++) {
        const int cur = kt & 1;
        float* Ac = As + cur * TILE * AST;
        float* Bc = Bs + cur * TILE * AST;
        if (kt + 1 < nk2) {
            size_t off = (size_t)(kt + 1) * BK;
            pa0 = *(const float4*)(Ag + off);
            pa1 = *(const float4*)(Ag + off + (size_t)64 * lda);
            pb0 = *(const float4*)(Bg + off);
            pb1 = *(const float4*)(Bg + off + (size_t)64 * ldb);
        }

        #pragma unroll
        for (int ks = 0; ks < BK; ks += 8) {
            uint32_t af[4][4], bf[4][2];
            #pragma unroll
            for (int mf = 0; mf < 4; mf++) {
                int row = wm0 + mf * 16 + (lane >> 2);
                int col = ks + (lane & 3);
                const float* p = &Ac[row * AST + col];
                af[mf][0] = f2tf(p[0]);
                af[mf][1] = f2tf(p[8 * AST]);
                af[mf][2] = f2tf(p[4]);
                af[mf][3] = f2tf(p[8 * AST + 4]);
            }
            #pragma unroll
            for (int nf = 0; nf < 4; nf++) {
                int row = wn0 + nf * 8 + (lane >> 2);
                int col = ks + (lane & 3);
                const float* p = &Bc[row * AST + col];
                bf[nf][0] = f2tf(p[0]);
                bf[nf][1] = f2tf(p[4]);
            }
            #pragma unroll
            for (int mf = 0; mf < 4; mf++)
                #pragma unroll
                for (int nf = 0; nf < 4; nf++)
                    mma8(acc[mf][nf], af[mf], bf[nf]);
        }

        if (kt + 1 < nk2) {
            float* An = As + (1 - cur) * TILE * AST;
            float* Bn = Bs + (1 - cur) * TILE * AST;
            *(float4*)&An[r0 * AST + c0]        = pa0;
            *(float4*)&An[(r0 + 64) * AST + c0] = pa1;
            *(float4*)&Bn[r0 * AST + c0]        = pb0;
            *(float4*)&Bn[(r0 + 64) * AST + c0] = pb1;
        }
        __syncthreads();
    }

    #pragma unroll
    for (int mf = 0; mf < 4; mf++) {
        int r = brow + wm0 + mf * 16 + (lane >> 2);
        #pragma unroll
        for (int nf = 0; nf < 4; nf++) {
            int cidx = bcol + wn0 + nf * 8 + (lane & 3) * 2;
            float b0 = 0.f, b1 = 0.f;
            if (bias) { b0 = bias[cidx]; b1 = bias[cidx + 1]; }
            float o0 = acc[mf][nf][0] + b0, o1 = acc[mf][nf][1] + b1;
            float o2 = acc[mf][nf][2] + b0, o3 = acc[mf][nf][3] + b1;
            if (round_out) { o0 = tf32r(o0); o1 = tf32r(o1); o2 = tf32r(o2); o3 = tf32r(o3); }
            *(float2*)&C[(size_t)r * ldc + cidx]       = make_float2(o0, o1);
            *(float2*)&C[(size_t)(r + 8) * ldc + cidx] = make_float2(o2, o3);
        }
    }
    #undef BK
    #undef AST
#endif
}

// ---------------------------------------------------------------------------
// Prepass: tf32-round copy (float4 vectorized)
// ---------------------------------------------------------------------------
__global__ void round_copy_kernel(const float4* __restrict__ src,
                                  float4* __restrict__ dst, int n4)
{
    int i = blockIdx.x * blockDim.x + threadIdx.x;
    if (i < n4) {
        float4 v = src[i];
        v.x = tf32r(v.x); v.y = tf32r(v.y); v.z = tf32r(v.z); v.w = tf32r(v.w);
        dst[i] = v;
    }
}

// ---------------------------------------------------------------------------
// Prepass: transpose + round: value [B,S,D] -> vt [B,D,S]
// ---------------------------------------------------------------------------
__global__ void transpose_round_kernel(const float* __restrict__ src,
                                       float* __restrict__ dst)
{
    __shared__ float t[32][33];
    const int b  = blockIdx.z;
    const int s0 = blockIdx.x * 32;
    const int d0 = blockIdx.y * 32;
    src += (size_t)b * SEQ * DIM;
    dst += (size_t)b * SEQ * DIM;
    const int tx = threadIdx.x, ty = threadIdx.y;
    #pragma unroll
    for (int j = 0; j < 32; j += 8)
        t[ty + j][tx] = src[(size_t)(s0 + ty + j) * DIM + d0 + tx];
    __syncthreads();
    #pragma unroll
    for (int j = 0; j < 32; j += 8)
        dst[(size_t)(d0 + ty + j) * SEQ + s0 + tx] = tf32r(t[tx][ty + j]);
}

// ---------------------------------------------------------------------------
// Row softmax over 2048 cols, scale folded in, output tf32-rounded, in place.
// ---------------------------------------------------------------------------
__global__ void softmax_kernel(float* __restrict__ x)
{
    const int row = blockIdx.x;
    float* p = x + (size_t)row * SEQ;
    const int tid = threadIdx.x;

    float v[8];
    float m = -1e30f;
    #pragma unroll
    for (int i = 0; i < 8; i++) {
        v[i] = p[tid + i * 256];
        m = fmaxf(m, v[i]);
    }

    __shared__ float red[8];
    #pragma unroll
    for (int o = 16; o; o >>= 1) m = fmaxf(m, __shfl_xor_sync(0xffffffffu, m, o));
    if ((tid & 31) == 0) red[tid >> 5] = m;
    __syncthreads();
    m = red[0];
    #pragma unroll
    for (int i = 1; i < 8; i++) m = fmaxf(m, red[i]);
    __syncthreads();

    float s = 0.f;
    #pragma unroll
    for (int i = 0; i < 8; i++) {
        v[i] = __expf((v[i] - m) * SOFTMAX_SCALE);
        s += v[i];
    }
    #pragma unroll
    for (int o = 16; o; o >>= 1) s += __shfl_xor_sync(0xffffffffu, s, o);
    if ((tid & 31) == 0) red[tid >> 5] = s;
    __syncthreads();
    s = red[0];
    #pragma unroll
    for (int i = 1; i < 8; i++) s += red[i];
    const float inv = 1.0f / s;

    #pragma unroll
    for (int i = 0; i < 8; i++) p[tid + i * 256] = tf32r(v[i] * inv);
}

// ---------------------------------------------------------------------------
extern "C" void kernel_launch(void* const* d_in, const int* in_sizes, int n_in,
                              void* d_out, int out_size)
{
    const float* query  = (const float*)d_in[0];
    const float* key_in = (const float*)d_in[1];
    const float* value  = (const float*)d_in[2];
    const float* Wq     = (const float*)d_in[3];
    const float* bq     = (const float*)d_in[4];
    const float* Wk     = (const float*)d_in[5];
    const float* bk     = (const float*)d_in[6];
    // Wv/bv (d_in[7], d_in[8]) are intentionally unused (reference quirk).
    float* out = (float*)d_out;

    float *qr, *kr, *wq, *wk, *vt, *q, *k, *dots;
    cudaGetSymbolAddress((void**)&qr, g_qr);
    cudaGetSymbolAddress((void**)&kr, g_kr);
    cudaGetSymbolAddress((void**)&wq, g_wq);
    cudaGetSymbolAddress((void**)&wk, g_wk);
    cudaGetSymbolAddress((void**)&vt, g_vt);
    cudaGetSymbolAddress((void**)&q,  g_q);
    cudaGetSymbolAddress((void**)&k,  g_k);
    cudaGetSymbolAddress((void**)&dots, g_dots);

    cudaFuncSetAttribute(gemm_u_kernel,
                         cudaFuncAttributeMaxDynamicSharedMemorySize, SMEM_TOTAL);

    // Prepass: tf32-round all raw MMA operands
    const int nBig = BATCH * SEQ * DIM / 4;
    const int nW   = DIM * DIM / 4;
    round_copy_kernel<<<(nBig + 255) / 256, 256>>>((const float4*)query,  (float4*)qr, nBig);
    round_copy_kernel<<<(nBig + 255) / 256, 256>>>((const float4*)key_in, (float4*)kr, nBig);
    round_copy_kernel<<<(nW + 255) / 256, 256>>>((const float4*)Wq, (float4*)wq, nW);
    round_copy_kernel<<<(nW + 255) / 256, 256>>>((const float4*)Wk, (float4*)wk, nW);
    transpose_round_kernel<<<dim3(SEQ / 32, DIM / 32, BATCH), dim3(32, 8)>>>(value, vt);

    // 1) q = query @ Wq^T + bq  (M=8192, N=1024, K=1024), round output
    gemm_u_kernel<<<dim3(DIM / TILE, (BATCH * SEQ) / TILE, 1), 256, SMEM_TOTAL>>>(
        qr, wq, bq, q, DIM, DIM, DIM, DIM / 32, 0, 0, 0, 1);

    // 2) k = key_in @ Wk^T + bk
    gemm_u_kernel<<<dim3(DIM / TILE, (BATCH * SEQ) / TILE, 1), 256, SMEM_TOTAL>>>(
        kr, wk, bk, k, DIM, DIM, DIM, DIM / 32, 0, 0, 0, 1);

    // 3) dots[b] = q[b] @ k[b]^T  (M=N=2048, K=1024)
    gemm_u_kernel<<<dim3(SEQ / TILE, SEQ / TILE, BATCH), 256, SMEM_TOTAL>>>(
        q, k, nullptr, dots, DIM, DIM, SEQ, DIM / 32,
        (size_t)SEQ * DIM, (size_t)SEQ * DIM, (size_t)SEQ * SEQ, 0);

    // 4) softmax rows (scale folded in, output rounded)
    softmax_kernel<<<BATCH * SEQ, 256>>>(dots);

    // 5) out[b] = attn[b] @ vt[b]^T  (M=2048, N=1024, K=2048)
    gemm_u_kernel<<<dim3(DIM / TILE, SEQ / TILE, BATCH), 256, SMEM_TOTAL>>>(
        dots, vt, nullptr, out, SEQ, SEQ, DIM, SEQ / 32,
        (size_t)SEQ * SEQ, (size_t)SEQ * DIM, (size_t)SEQ * DIM, 0);
}